// round 8
// baseline (speedup 1.0000x reference)
#include <cuda_runtime.h>
#include <cuda_bf16.h>

// CenterLoss: loss = mean_b sum_d (features[b,d] - centers[labels[b],d])^2
// B=65536, D=256, C=100000. HBM-bound gather + reduction.
// Stage1 (147 SMs x 8 CTAs): R5-proven mainloop (__ldcs features, pipelined
//   labels). PDL trigger at ENTRY; each CTA publishes partial + release-flag.
// Stage2 (1 CTA on the deliberately-free 148th SM): launches concurrently,
//   acquire-polls per-CTA flags, consumes partials as they land, resets flags
//   for the next graph replay. Tail = poll latency, not launch latency.

#define BATCH    65536
#define FEAT_DIM 256
#define GRID1    1176          // 147 SMs * 8 CTAs — one SM left free for stage2
#define BLOCK1   256           // 8 warps per CTA
#define NWARPS   ((GRID1 * BLOCK1) >> 5)   // 9408

__device__ __align__(16) float g_partials[GRID1];
__device__ int g_flags[GRID1];             // zero-initialized at module load

__device__ __forceinline__ void store_release_gpu_i(int* p, int v) {
    asm volatile("st.global.release.gpu.s32 [%0], %1;" :: "l"(p), "r"(v) : "memory");
}
__device__ __forceinline__ int load_acquire_gpu_i(const int* p) {
    int v;
    asm volatile("ld.global.acquire.gpu.s32 %0, [%1];" : "=r"(v) : "l"(p) : "memory");
    return v;
}

__global__ __launch_bounds__(BLOCK1, 8) void center_loss_stage1(
    const float* __restrict__ features,
    const int*   __restrict__ labels,
    const float* __restrict__ centers)
{
    // Fire the dependent launch immediately: stage2 starts polling while we work.
    cudaTriggerProgrammaticLaunchCompletion();

    const int lane   = threadIdx.x & 31;
    const int wid    = threadIdx.x >> 5;
    const int warp_g = (blockIdx.x * BLOCK1 + threadIdx.x) >> 5;

    float acc = 0.0f;

    int row = warp_g;
    int lbl = (row < BATCH) ? __ldcs(labels + row) : 0;   // pipelined label

    for (; row < BATCH; ) {
        const int next_row = row + NWARPS;
        const int next_lbl = (next_row < BATCH) ? __ldcs(labels + next_row) : 0;

        const float4* __restrict__ f =
            reinterpret_cast<const float4*>(features + (size_t)row * FEAT_DIM);
        const float4* __restrict__ c =
            reinterpret_cast<const float4*>(centers + (size_t)lbl * FEAT_DIM);

        // 256 floats/row = 64 float4; 32 lanes * 2 float4 each.
        float4 f0 = __ldcs(f + lane);          // features: streaming, no reuse
        float4 f1 = __ldcs(f + lane + 32);
        float4 c0 = __ldg(c + lane);           // centers: cached, repeats hit L2
        float4 c1 = __ldg(c + lane + 32);

        float d;
        d = f0.x - c0.x; acc = fmaf(d, d, acc);
        d = f0.y - c0.y; acc = fmaf(d, d, acc);
        d = f0.z - c0.z; acc = fmaf(d, d, acc);
        d = f0.w - c0.w; acc = fmaf(d, d, acc);
        d = f1.x - c1.x; acc = fmaf(d, d, acc);
        d = f1.y - c1.y; acc = fmaf(d, d, acc);
        d = f1.z - c1.z; acc = fmaf(d, d, acc);
        d = f1.w - c1.w; acc = fmaf(d, d, acc);

        row = next_row;
        lbl = next_lbl;
    }

    // warp reduce
    #pragma unroll
    for (int o = 16; o > 0; o >>= 1)
        acc += __shfl_xor_sync(0xFFFFFFFFu, acc, o);

    __shared__ float smem[BLOCK1 / 32];
    if (lane == 0) smem[wid] = acc;
    __syncthreads();

    if (threadIdx.x == 0) {
        float v = 0.0f;
        #pragma unroll
        for (int i = 0; i < BLOCK1 / 32; i++) v += smem[i];
        g_partials[blockIdx.x] = v;                    // plain store
        store_release_gpu_i(&g_flags[blockIdx.x], 1);  // release: partial visible first
    }
}

__global__ __launch_bounds__(1024) void center_loss_stage2(float* __restrict__ out)
{
    // Runs concurrently with stage1 (trigger fired at stage1 entry).
    const int tid = threadIdx.x;

    float acc = 0.0f;

    // Each thread owns partial indices tid and tid+1024 (GRID1=1176 < 2048).
    #pragma unroll
    for (int k = 0; k < 2; k++) {
        const int idx = tid + k * 1024;
        if (idx < GRID1) {
            while (load_acquire_gpu_i(&g_flags[idx]) == 0) { /* spin */ }
            acc += g_partials[idx];
            g_flags[idx] = 0;   // reset for next graph replay (stream-ordered)
        }
    }

    #pragma unroll
    for (int o = 16; o > 0; o >>= 1)
        acc += __shfl_xor_sync(0xFFFFFFFFu, acc, o);

    __shared__ float smem[32];
    if ((tid & 31) == 0) smem[tid >> 5] = acc;
    __syncthreads();

    if (tid < 32) {
        float v = smem[tid];
        #pragma unroll
        for (int o = 16; o > 0; o >>= 1)
            v += __shfl_xor_sync(0xFFFFFFFFu, v, o);
        if (tid == 0)
            out[0] = v * (1.0f / (float)BATCH);   // LAMBDA_C = 1.0
    }
}

extern "C" void kernel_launch(void* const* d_in, const int* in_sizes, int n_in,
                              void* d_out, int out_size)
{
    const float* features = (const float*)d_in[0];
    const int*   labels   = (const int*)  d_in[1];
    const float* centers  = (const float*)d_in[2];
    float*       out      = (float*)d_out;

    center_loss_stage1<<<GRID1, BLOCK1>>>(features, labels, centers);

    cudaLaunchAttribute attrs[1];
    attrs[0].id = cudaLaunchAttributeProgrammaticStreamSerialization;
    attrs[0].val.programmaticStreamSerializationAllowed = 1;

    cudaLaunchConfig_t cfg = {};
    cfg.gridDim  = dim3(1, 1, 1);
    cfg.blockDim = dim3(1024, 1, 1);
    cfg.dynamicSmemBytes = 0;
    cfg.stream   = 0;
    cfg.attrs    = attrs;
    cfg.numAttrs = 1;

    cudaLaunchKernelEx(&cfg, center_loss_stage2, out);
}